// round 11
// baseline (speedup 1.0000x reference)
#include <cuda_runtime.h>
#include <cstdint>

#define KDIM   8192
#define TPB    512
#define MAXC   100
#define MINC   20
#define CAP    2048
#define EQCAP  256
#define SAMP_K 24

__device__ __forceinline__ unsigned fkey(float f) {
    unsigned u = __float_as_uint(f);
    return u ^ (unsigned)(((int)u >> 31) | 0x80000000);
}

// warp-0-only: find digit d (descending) where the suffix count crosses kk.
// Writes shPrefix = pref | d<<shift, shKK = kk - count(bins > d), shBin = hist[d].
__device__ __forceinline__ void scan_crossing(const int* __restrict__ h, int kk,
                                              unsigned pref, int shift,
                                              unsigned* shPrefix, int* shKK, int* shBin)
{
    int lane = threadIdx.x & 31;
    int base = 255 - lane * 8;          // lane covers digits base .. base-7 (descending)
    int loc[8], tot = 0;
    #pragma unroll
    for (int t = 0; t < 8; t++) { loc[t] = h[base - t]; tot += loc[t]; }
    int inc = tot;
    #pragma unroll
    for (int o = 1; o < 32; o <<= 1) {
        int v = __shfl_up_sync(0xffffffffu, inc, o);
        if (lane >= o) inc += v;
    }
    int run = inc - tot;                // total count in digits above my block
    #pragma unroll
    for (int t = 0; t < 8; t++) {
        int below = run; run += loc[t];
        if (run >= kk && below < kk) {
            *shKK     = kk - below;
            *shPrefix = pref | ((unsigned)(base - t) << shift);
            *shBin    = loc[t];
        }
    }
}

__global__ __launch_bounds__(TPB, 3)
void retention_kernel(const float* __restrict__ logits,
                      float* __restrict__ bs_out,
                      float* __restrict__ cls_out,
                      float* __restrict__ mask_out)
{
    __shared__ int      h6[6][256];        // 6 pre-zeroed histograms
    __shared__ unsigned cand_key[CAP];
    __shared__ int      cand_idx[CAP];
    __shared__ int      selA[128];
    __shared__ int      eqA[EQCAP];
    __shared__ int      selOut[MAXC];
    __shared__ int      warpTot[16];
    __shared__ int      shCount, shN, shKK, shBin, shSel, shEq;
    __shared__ unsigned shPrefix;

    const int tid  = threadIdx.x;
    const int lane = tid & 31;
    const int warp = tid >> 5;
    const int row  = blockIdx.x;

    for (int i = tid; i < 6 * 256; i += TPB) ((int*)h6)[i] = 0;
    if (tid == 0) { shCount = 0; shN = 0; shSel = 0; shEq = 0; }
    __syncthreads();

    const float*  rowp = logits + (size_t)row * KDIM;
    const float4* src4 = (const float4*)rowp;

    // ---- Sample phase: 512 strided samples -> 16-bit-granular pivot T0u
    unsigned sk = fkey(rowp[tid * 16]);
    {
        int b = (int)(sk >> 24);
        unsigned m = __match_any_sync(0xffffffffu, b);
        if ((__ffs(m) - 1) == lane) atomicAdd(&h6[0][b], __popc(m));
    }
    __syncthreads();
    if (warp == 0) scan_crossing(h6[0], SAMP_K, 0u, 24, &shPrefix, &shKK, &shBin);
    __syncthreads();
    {
        unsigned d1 = shPrefix >> 24;
        if ((sk >> 24) == d1) atomicAdd(&h6[1][(sk >> 16) & 255u], 1);
    }
    int kkL2 = shKK; unsigned prefL2 = shPrefix;
    __syncthreads();
    if (warp == 0) scan_crossing(h6[1], kkL2, prefL2, 16, &shPrefix, &shKK, &shBin);
    __syncthreads();
    const unsigned T0u = shPrefix;
    const float f0 = __uint_as_float((T0u & 0x80000000u) ? (T0u ^ 0x80000000u) : ~T0u);
    __syncthreads();

    // ---- Main sweep: count(>=0) + survivor push (float-domain compare, fkey only on push)
    int c0 = 0;
    #pragma unroll
    for (int j = 0; j < 4; j++) {
        float4 v = src4[tid + j * TPB];
        int bidx = (tid + j * TPB) * 4;
        c0 += (v.x >= 0.f) + (v.y >= 0.f) + (v.z >= 0.f) + (v.w >= 0.f);
        if (v.x >= f0) { int p = atomicAdd(&shN, 1); if (p < CAP) { cand_key[p] = fkey(v.x); cand_idx[p] = bidx;     } }
        if (v.y >= f0) { int p = atomicAdd(&shN, 1); if (p < CAP) { cand_key[p] = fkey(v.y); cand_idx[p] = bidx + 1; } }
        if (v.z >= f0) { int p = atomicAdd(&shN, 1); if (p < CAP) { cand_key[p] = fkey(v.z); cand_idx[p] = bidx + 2; } }
        if (v.w >= f0) { int p = atomicAdd(&shN, 1); if (p < CAP) { cand_key[p] = fkey(v.w); cand_idx[p] = bidx + 3; } }
    }
    #pragma unroll
    for (int o = 16; o; o >>= 1) c0 += __shfl_xor_sync(0xffffffffu, c0, o);
    if (lane == 0) atomicAdd(&shCount, c0);
    __syncthreads();

    const int numTrain = min(max(shCount, MINC), MAXC);
    const int n = shN;
    bool done = false;
    unsigned T = 0u; int nEq = 0;

    if (n <= CAP && n >= numTrain) {
        // ---- Fast path: exact 4-pass radix select over n candidates
        if (tid == 0) { shPrefix = 0u; shKK = numTrain; }
        __syncthreads();
        // pass 0 (match_any aggregation: bins are concentrated)
        {
            int iters = (n + TPB - 1) / TPB;
            for (int it = 0; it < iters; it++) {
                int i = tid + it * TPB;
                bool act = i < n;
                unsigned am = __ballot_sync(0xffffffffu, act);
                if (act) {
                    int b = (int)(cand_key[i] >> 24);
                    unsigned m = __match_any_sync(am, b);
                    if ((__ffs(m) - 1) == lane) atomicAdd(&h6[2][b], __popc(m));
                }
            }
        }
        __syncthreads();
        if (warp == 0) scan_crossing(h6[2], numTrain, 0u, 24, &shPrefix, &shKK, &shBin);
        __syncthreads();
        #pragma unroll 1
        for (int pp = 1; pp < 4; pp++) {
            const int shift = 24 - 8 * pp;
            const unsigned pref = shPrefix;
            const int kk = shKK;
            const unsigned prefHi = pref >> (shift + 8);
            for (int i = tid; i < n; i += TPB) {
                unsigned k = cand_key[i];
                if ((k >> (shift + 8)) == prefHi)
                    atomicAdd(&h6[2 + pp][(k >> shift) & 255u], 1);
            }
            __syncthreads();
            if (warp == 0) scan_crossing(h6[2 + pp], kk, pref, shift, &shPrefix, &shKK, &shBin);
            __syncthreads();
        }
        T = shPrefix; nEq = shKK;

        // gather selected (>T always; ==T into eqA for index tie-break)
        for (int i = tid; i < n; i += TPB) {
            unsigned k = cand_key[i];
            if (k > T)       { int p = atomicAdd(&shSel, 1); selA[p] = cand_idx[i]; }
            else if (k == T) { int p = atomicAdd(&shEq, 1); if (p < EQCAP) eqA[p] = cand_idx[i]; }
        }
        __syncthreads();
        int m = shEq;
        if (m <= EQCAP) {
            for (int i = tid; i < m; i += TPB) {
                int my = eqA[i], r = 0;
                for (int j2 = 0; j2 < m; j2++) r += (eqA[j2] < my);
                if (r < nEq) { int p = atomicAdd(&shSel, 1); selA[p] = my; }
            }
            __syncthreads();
            // rank the numTrain selected indices -> ascending order
            for (int i = tid; i < numTrain; i += TPB) {
                int my = selA[i], r = 0;
                for (int j2 = 0; j2 < numTrain; j2++) r += (selA[j2] < my);
                selOut[r] = my;
            }
            __syncthreads();
            done = true;
        }
    }

    if (!done) {
        // ---- Exact fallback: full 4-pass radix over gmem + ordered emission
        if (tid == 0) { shPrefix = 0u; shKK = numTrain; }
        __syncthreads();
        #pragma unroll 1
        for (int pp = 0; pp < 4; pp++) {
            if (tid < 256) h6[0][tid] = 0;
            __syncthreads();
            const int shift = 24 - 8 * pp;
            const unsigned pref = shPrefix;
            const int kk = shKK;
            const unsigned prefHi = (pp > 0) ? (pref >> (shift + 8)) : 0u;
            for (int i = tid; i < KDIM; i += TPB) {
                unsigned k = fkey(rowp[i]);
                bool act = (pp == 0) || ((k >> (shift + 8)) == prefHi);
                if (act) atomicAdd(&h6[0][(k >> shift) & 255u], 1);
            }
            __syncthreads();
            if (warp == 0) scan_crossing(h6[0], kk, pref, shift, &shPrefix, &shKK, &shBin);
            __syncthreads();
        }
        T = shPrefix; nEq = shKK;

        // ordered compaction: thread t owns elements [t*16, t*16+16)
        const float4* my4 = src4 + tid * 4;
        int cg = 0, ce = 0;
        #pragma unroll
        for (int j = 0; j < 4; j++) {
            float4 v = my4[j];
            unsigned k0 = fkey(v.x), k1 = fkey(v.y), k2 = fkey(v.z), k3 = fkey(v.w);
            cg += (k0 > T) + (k1 > T) + (k2 > T) + (k3 > T);
            ce += (k0 == T) + (k1 == T) + (k2 == T) + (k3 == T);
        }
        int pack = (cg << 16) | ce;
        int inc2 = pack;
        #pragma unroll
        for (int o = 1; o < 32; o <<= 1) {
            int t = __shfl_up_sync(0xffffffffu, inc2, o);
            if (lane >= o) inc2 += t;
        }
        if (lane == 31) warpTot[warp] = inc2;
        __syncthreads();
        int wOff = 0;
        #pragma unroll
        for (int w = 0; w < 16; w++) if (w < warp) wOff += warpTot[w];
        int exc = wOff + inc2 - pack;
        int g = exc >> 16;
        int e = exc & 0xFFFF;
        #pragma unroll
        for (int j = 0; j < 4; j++) {
            float4 v = my4[j];
            #pragma unroll
            for (int c = 0; c < 4; c++) {
                float f = (c == 0) ? v.x : (c == 1) ? v.y : (c == 2) ? v.z : v.w;
                unsigned k = fkey(f);
                int idx = tid * 16 + j * 4 + c;
                if (k > T)       { selOut[g + min(e, nEq)] = idx; g++; }
                else if (k == T) { if (e < nEq) selOut[g + e] = idx; e++; }
            }
        }
        __syncthreads();
    }

    // ---- Emit float32 [bs_idx | cls_idx | mask]
    if (tid < MAXC) {
        bool valid = tid < numTrain;
        size_t o = (size_t)row * MAXC + tid;
        bs_out[o]   = valid ? (float)row         : -1.0f;
        cls_out[o]  = valid ? (float)selOut[tid] : -1.0f;
        mask_out[o] = valid ? 1.0f : 0.0f;
    }
}

extern "C" void kernel_launch(void* const* d_in, const int* in_sizes, int n_in,
                              void* d_out, int out_size) {
    const float* logits = (const float*)d_in[0];
    const int total = in_sizes[0];
    const int bs = total / KDIM;
    const size_t per = (size_t)bs * MAXC;

    float* out = (float*)d_out;
    float* bs_out   = out;
    float* cls_out  = out + per;
    float* mask_out = out + 2 * per;

    retention_kernel<<<bs, TPB>>>(logits, bs_out, cls_out, mask_out);
}

// round 12
// speedup vs baseline: 1.2306x; 1.2306x over previous
#include <cuda_runtime.h>
#include <cstdint>

#define KDIM   8192
#define TPB    256
#define MAXC   100
#define MINC   20
#define CAP    2048
#define EQCAP  256
#define SAMP_K 16

__device__ __forceinline__ unsigned fkey(float f) {
    unsigned u = __float_as_uint(f);
    return u ^ (unsigned)(((int)u >> 31) | 0x80000000);
}

// warp-0-only: find digit d (descending) where the suffix count crosses kk.
__device__ __forceinline__ void scan_crossing(const int* __restrict__ h, int kk,
                                              unsigned pref, int shift,
                                              unsigned* shPrefix, int* shKK, int* shBin)
{
    int lane = threadIdx.x & 31;
    int base = 255 - lane * 8;          // lane covers digits base .. base-7 (descending)
    int loc[8], tot = 0;
    #pragma unroll
    for (int t = 0; t < 8; t++) { loc[t] = h[base - t]; tot += loc[t]; }
    int inc = tot;
    #pragma unroll
    for (int o = 1; o < 32; o <<= 1) {
        int v = __shfl_up_sync(0xffffffffu, inc, o);
        if (lane >= o) inc += v;
    }
    int run = inc - tot;                // count in digits above my block
    #pragma unroll
    for (int t = 0; t < 8; t++) {
        int below = run; run += loc[t];
        if (run >= kk && below < kk) {
            *shKK     = kk - below;
            *shPrefix = pref | ((unsigned)(base - t) << shift);
            *shBin    = loc[t];
        }
    }
}

__global__ __launch_bounds__(TPB, 6)
void retention_kernel(const float* __restrict__ logits,
                      float* __restrict__ bs_out,
                      float* __restrict__ cls_out,
                      float* __restrict__ mask_out)
{
    __shared__ int      h6[6][256];
    __shared__ unsigned cand_key[CAP];
    __shared__ int      cand_idx[CAP];
    __shared__ int      selA[128];
    __shared__ int      eqA[EQCAP];
    __shared__ int      selOut[MAXC];
    __shared__ int      warpTot[8];
    __shared__ int      shCount, shN, shKK, shBin, shSel, shEq;
    __shared__ unsigned shPrefix;

    const int tid  = threadIdx.x;
    const int lane = tid & 31;
    const int warp = tid >> 5;
    const int row  = blockIdx.x;

    h6[0][tid] = 0; h6[1][tid] = 0;
    if (tid == 0) { shCount = 0; shN = 0; shSel = 0; shEq = 0; }
    __syncthreads();

    const float*  rowp = logits + (size_t)row * KDIM;
    const float4* src4 = (const float4*)rowp;

    // ---- Sample phase: FREE samples — .x of the float4 each thread loads anyway.
    float4 v0 = src4[tid];                  // elements [4*tid, 4*tid+4), coalesced
    unsigned sk = fkey(v0.x);               // 256 samples, zero extra L1 traffic
    {
        int b = (int)(sk >> 24);
        unsigned m = __match_any_sync(0xffffffffu, b);
        if ((__ffs(m) - 1) == lane) atomicAdd(&h6[0][b], __popc(m));
    }
    __syncthreads();
    if (warp == 0) scan_crossing(h6[0], SAMP_K, 0u, 24, &shPrefix, &shKK, &shBin);
    __syncthreads();
    if ((sk >> 24) == (shPrefix >> 24)) atomicAdd(&h6[1][(sk >> 16) & 255u], 1);
    const int kkL2 = shKK; const unsigned prefL2 = shPrefix;
    __syncthreads();
    if (warp == 0) scan_crossing(h6[1], kkL2, prefL2, 16, &shPrefix, &shKK, &shBin);
    __syncthreads();
    const unsigned T0u = shPrefix;          // 16-bit-granular pivot key
    const float f0 = __uint_as_float((T0u & 0x80000000u) ? (T0u ^ 0x80000000u) : ~T0u);

    // zero radix histograms while nothing depends on them yet
    h6[2][tid] = 0; h6[3][tid] = 0; h6[4][tid] = 0; h6[5][tid] = 0;

    // ---- Main sweep: count(>=0) + warp-aggregated survivor push
    const unsigned ltm = (1u << lane) - 1u;
    int cw = 0;                              // warp-uniform running count
    #pragma unroll
    for (int j = 0; j < 8; j++) {
        float4 v = (j == 0) ? v0 : src4[tid + j * TPB];
        const int bidx = (tid + j * TPB) * 4;
        unsigned z0 = __ballot_sync(0xffffffffu, v.x >= 0.f);
        unsigned z1 = __ballot_sync(0xffffffffu, v.y >= 0.f);
        unsigned z2 = __ballot_sync(0xffffffffu, v.z >= 0.f);
        unsigned z3 = __ballot_sync(0xffffffffu, v.w >= 0.f);
        cw += __popc(z0) + __popc(z1) + __popc(z2) + __popc(z3);
        unsigned p0 = __ballot_sync(0xffffffffu, v.x >= f0);
        unsigned p1 = __ballot_sync(0xffffffffu, v.y >= f0);
        unsigned p2 = __ballot_sync(0xffffffffu, v.z >= f0);
        unsigned p3 = __ballot_sync(0xffffffffu, v.w >= f0);
        int n0 = __popc(p0), n1 = __popc(p1), n2 = __popc(p2), n3 = __popc(p3);
        int tot = n0 + n1 + n2 + n3;
        int base = 0;
        if (lane == 0 && tot) base = atomicAdd(&shN, tot);
        base = __shfl_sync(0xffffffffu, base, 0);
        int o0 = base + __popc(p0 & ltm);
        int o1 = base + n0 + __popc(p1 & ltm);
        int o2 = base + n0 + n1 + __popc(p2 & ltm);
        int o3 = base + n0 + n1 + n2 + __popc(p3 & ltm);
        if (((p0 >> lane) & 1) && o0 < CAP) { cand_key[o0] = fkey(v.x); cand_idx[o0] = bidx;     }
        if (((p1 >> lane) & 1) && o1 < CAP) { cand_key[o1] = fkey(v.y); cand_idx[o1] = bidx + 1; }
        if (((p2 >> lane) & 1) && o2 < CAP) { cand_key[o2] = fkey(v.z); cand_idx[o2] = bidx + 2; }
        if (((p3 >> lane) & 1) && o3 < CAP) { cand_key[o3] = fkey(v.w); cand_idx[o3] = bidx + 3; }
    }
    if (lane == 0) atomicAdd(&shCount, cw);
    __syncthreads();

    const int numTrain = min(max(shCount, MINC), MAXC);
    const int n = shN;
    bool done = false;
    unsigned T = 0u; int nEq = 0;

    if (n <= CAP && n >= numTrain) {
        // ---- Fast path: exact 4-pass radix select over n candidates (n ~ 500)
        if (tid == 0) { shPrefix = 0u; shKK = numTrain; }
        __syncthreads();
        {
            int iters = (n + TPB - 1) / TPB;
            for (int it = 0; it < iters; it++) {
                int i = tid + it * TPB;
                bool act = i < n;
                unsigned am = __ballot_sync(0xffffffffu, act);
                if (act) {
                    int b = (int)(cand_key[i] >> 24);
                    unsigned m = __match_any_sync(am, b);
                    if ((__ffs(m) - 1) == lane) atomicAdd(&h6[2][b], __popc(m));
                }
            }
        }
        __syncthreads();
        if (warp == 0) scan_crossing(h6[2], numTrain, 0u, 24, &shPrefix, &shKK, &shBin);
        __syncthreads();
        #pragma unroll 1
        for (int pp = 1; pp < 4; pp++) {
            const int shift = 24 - 8 * pp;
            const unsigned pref = shPrefix;
            const int kk = shKK;
            const unsigned prefHi = pref >> (shift + 8);
            for (int i = tid; i < n; i += TPB) {
                unsigned k = cand_key[i];
                if ((k >> (shift + 8)) == prefHi)
                    atomicAdd(&h6[2 + pp][(k >> shift) & 255u], 1);
            }
            __syncthreads();
            if (warp == 0) scan_crossing(h6[2 + pp], kk, pref, shift, &shPrefix, &shKK, &shBin);
            __syncthreads();
        }
        T = shPrefix; nEq = shKK;

        // gather selected (>T always; ==T ranked by index, keep lowest nEq)
        for (int i = tid; i < n; i += TPB) {
            unsigned k = cand_key[i];
            if (k > T)       { int p = atomicAdd(&shSel, 1); selA[p] = cand_idx[i]; }
            else if (k == T) { int p = atomicAdd(&shEq, 1); if (p < EQCAP) eqA[p] = cand_idx[i]; }
        }
        __syncthreads();
        int m = shEq;
        if (m <= EQCAP) {
            for (int i = tid; i < m; i += TPB) {
                int my = eqA[i], r = 0;
                for (int j2 = 0; j2 < m; j2++) r += (eqA[j2] < my);
                if (r < nEq) { int p = atomicAdd(&shSel, 1); selA[p] = my; }
            }
            __syncthreads();
            for (int i = tid; i < numTrain; i += TPB) {
                int my = selA[i], r = 0;
                for (int j2 = 0; j2 < numTrain; j2++) r += (selA[j2] < my);
                selOut[r] = my;
            }
            __syncthreads();
            done = true;
        }
    }

    if (!done) {
        // ---- Exact fallback: full 4-pass radix over gmem + ordered emission
        if (tid == 0) { shPrefix = 0u; shKK = numTrain; }
        __syncthreads();
        #pragma unroll 1
        for (int pp = 0; pp < 4; pp++) {
            h6[0][tid] = 0;
            __syncthreads();
            const int shift = 24 - 8 * pp;
            const unsigned pref = shPrefix;
            const int kk = shKK;
            const unsigned prefHi = (pp > 0) ? (pref >> (shift + 8)) : 0u;
            for (int i = tid; i < KDIM; i += TPB) {
                unsigned k = fkey(rowp[i]);
                if ((pp == 0) || ((k >> (shift + 8)) == prefHi))
                    atomicAdd(&h6[0][(k >> shift) & 255u], 1);
            }
            __syncthreads();
            if (warp == 0) scan_crossing(h6[0], kk, pref, shift, &shPrefix, &shKK, &shBin);
            __syncthreads();
        }
        T = shPrefix; nEq = shKK;

        // ordered compaction: thread t owns elements [t*32, t*32+32)
        const float4* my4 = src4 + tid * 8;
        int cg = 0, ce = 0;
        #pragma unroll
        for (int j = 0; j < 8; j++) {
            float4 v = my4[j];
            unsigned k0 = fkey(v.x), k1 = fkey(v.y), k2 = fkey(v.z), k3 = fkey(v.w);
            cg += (k0 > T) + (k1 > T) + (k2 > T) + (k3 > T);
            ce += (k0 == T) + (k1 == T) + (k2 == T) + (k3 == T);
        }
        int pack = (cg << 16) | ce;
        int inc2 = pack;
        #pragma unroll
        for (int o = 1; o < 32; o <<= 1) {
            int t = __shfl_up_sync(0xffffffffu, inc2, o);
            if (lane >= o) inc2 += t;
        }
        if (lane == 31) warpTot[warp] = inc2;
        __syncthreads();
        int wOff = 0;
        #pragma unroll
        for (int w = 0; w < 8; w++) if (w < warp) wOff += warpTot[w];
        int exc = wOff + inc2 - pack;
        int g = exc >> 16;
        int e = exc & 0xFFFF;
        #pragma unroll
        for (int j = 0; j < 8; j++) {
            float4 v = my4[j];
            #pragma unroll
            for (int c = 0; c < 4; c++) {
                float f = (c == 0) ? v.x : (c == 1) ? v.y : (c == 2) ? v.z : v.w;
                unsigned k = fkey(f);
                int idx = tid * 32 + j * 4 + c;
                if (k > T)       { selOut[g + min(e, nEq)] = idx; g++; }
                else if (k == T) { if (e < nEq) selOut[g + e] = idx; e++; }
            }
        }
        __syncthreads();
    }

    // ---- Emit float32 [bs_idx | cls_idx | mask]
    if (tid < MAXC) {
        bool valid = tid < numTrain;
        size_t o = (size_t)row * MAXC + tid;
        bs_out[o]   = valid ? (float)row         : -1.0f;
        cls_out[o]  = valid ? (float)selOut[tid] : -1.0f;
        mask_out[o] = valid ? 1.0f : 0.0f;
    }
}

extern "C" void kernel_launch(void* const* d_in, const int* in_sizes, int n_in,
                              void* d_out, int out_size) {
    const float* logits = (const float*)d_in[0];
    const int total = in_sizes[0];
    const int bs = total / KDIM;
    const size_t per = (size_t)bs * MAXC;

    float* out = (float*)d_out;
    float* bs_out   = out;
    float* cls_out  = out + per;
    float* mask_out = out + 2 * per;

    retention_kernel<<<bs, TPB>>>(logits, bs_out, cls_out, mask_out);
}

// round 17
// speedup vs baseline: 1.3982x; 1.1362x over previous
#include <cuda_runtime.h>
#include <cstdint>

#define KDIM   8192
#define TPB    256
#define MAXC   100
#define MINC   20
#define CAP    2048
#define EQCAP  256
#define SAMP_K 16

__device__ __forceinline__ unsigned fkey(float f) {
    unsigned u = __float_as_uint(f);
    return u ^ (unsigned)(((int)u >> 31) | 0x80000000);
}
__device__ __forceinline__ unsigned fkey_raw(unsigned u) {
    return u ^ (unsigned)(((int)u >> 31) | 0x80000000);
}

// warp0: plain crossing search for kk over 256-bin hist (descending digits).
__device__ __forceinline__ void scan_crossing(const int* __restrict__ h, int kk,
                                              unsigned pref, int shift,
                                              unsigned* shPrefix, int* shKK)
{
    int lane = threadIdx.x & 31;
    int base = 255 - lane * 8;
    int loc[8], tot = 0;
    #pragma unroll
    for (int t = 0; t < 8; t++) { loc[t] = h[base - t]; tot += loc[t]; }
    int inc = tot;
    #pragma unroll
    for (int o = 1; o < 32; o <<= 1) {
        int v = __shfl_up_sync(0xffffffffu, inc, o);
        if (lane >= o) inc += v;
    }
    int run = inc - tot;
    #pragma unroll
    for (int t = 0; t < 8; t++) {
        int below = run; run += loc[t];
        if (run >= kk && below < kk) {
            *shKK     = kk - below;
            *shPrefix = pref | ((unsigned)(base - t) << shift);
        }
    }
}

// warp0: same, but first derives count(>=0) = sum of bins 128..255 (lane15's
// inclusive sum), clamps it to numTrain, publishes it, then does the crossing.
__device__ __forceinline__ void scan_count_cross(const int* __restrict__ h,
                                                 unsigned* shPrefix, int* shKK,
                                                 int* shNum)
{
    int lane = threadIdx.x & 31;
    int base = 255 - lane * 8;
    int loc[8], tot = 0;
    #pragma unroll
    for (int t = 0; t < 8; t++) { loc[t] = h[base - t]; tot += loc[t]; }
    int inc = tot;
    #pragma unroll
    for (int o = 1; o < 32; o <<= 1) {
        int v = __shfl_up_sync(0xffffffffu, inc, o);
        if (lane >= o) inc += v;
    }
    int cntPos = __shfl_sync(0xffffffffu, inc, 15);   // bins 128..255
    int kk = min(max(cntPos, MINC), MAXC);
    if (lane == 0) *shNum = kk;
    int run = inc - tot;
    #pragma unroll
    for (int t = 0; t < 8; t++) {
        int below = run; run += loc[t];
        if (run >= kk && below < kk) {
            *shKK     = kk - below;
            *shPrefix = ((unsigned)(base - t) << 24);
        }
    }
}

__global__ __launch_bounds__(TPB, 6)
void retention_kernel(const float* __restrict__ logits,
                      float* __restrict__ bs_out,
                      float* __restrict__ cls_out,
                      float* __restrict__ mask_out)
{
    __shared__ int      h6[6][256];
    __shared__ uint2    cand[CAP];         // {raw float bits -> fkey in-place, idx}
    __shared__ int      selA[128];
    __shared__ int      eqA[EQCAP];
    __shared__ int      warpTot[8];
    __shared__ int      shN, shKK, shSel, shEq, shNum;
    __shared__ unsigned shPrefix;

    const int tid  = threadIdx.x;
    const int lane = tid & 31;
    const int warp = tid >> 5;
    const int row  = blockIdx.x;
    const size_t obase = (size_t)row * MAXC;

    h6[0][tid] = 0; h6[1][tid] = 0;
    h6[2][tid] = 0; h6[3][tid] = 0; h6[4][tid] = 0; h6[5][tid] = 0;
    if (tid == 0) { shN = 0; shSel = 0; shEq = 0; }
    __syncthreads();

    const float*  rowp = logits + (size_t)row * KDIM;
    const float4* src4 = (const float4*)rowp;

    // ---- Sample phase: free samples (.x of the float4 we must load anyway)
    float4 v0 = src4[tid];
    unsigned sk = fkey(v0.x);
    {
        int b = (int)(sk >> 24);
        unsigned m = __match_any_sync(0xffffffffu, b);
        if ((__ffs(m) - 1) == lane) atomicAdd(&h6[0][b], __popc(m));
    }
    __syncthreads();
    if (warp == 0) scan_crossing(h6[0], SAMP_K, 0u, 24, &shPrefix, &shKK);
    __syncthreads();
    if ((sk >> 24) == (shPrefix >> 24)) atomicAdd(&h6[1][(sk >> 16) & 255u], 1);
    const int kkL2 = shKK; const unsigned prefL2 = shPrefix;
    __syncthreads();
    if (warp == 0) scan_crossing(h6[1], kkL2, prefL2, 16, &shPrefix, &shKK);
    __syncthreads();
    const unsigned T0u = shPrefix;
    const float f0 = __uint_as_float((T0u & 0x80000000u) ? (T0u ^ 0x80000000u) : ~T0u);

    // ---- Main sweep: compare-only + rare candidate push (raw bits, no fkey)
    #pragma unroll
    for (int j = 0; j < 8; j++) {
        float4 v = (j == 0) ? v0 : src4[tid + j * TPB];
        const int bidx = (tid + j * TPB) * 4;
        int b0 = v.x >= f0, b1 = v.y >= f0, b2 = v.z >= f0, b3 = v.w >= f0;
        int cnt = b0 + b1 + b2 + b3;
        if (cnt) {
            int p = atomicAdd(&shN, cnt);
            if (b0) { if (p < CAP) cand[p] = make_uint2(__float_as_uint(v.x), bidx    ); p++; }
            if (b1) { if (p < CAP) cand[p] = make_uint2(__float_as_uint(v.y), bidx + 1); p++; }
            if (b2) { if (p < CAP) cand[p] = make_uint2(__float_as_uint(v.z), bidx + 2); p++; }
            if (b3) { if (p < CAP) cand[p] = make_uint2(__float_as_uint(v.w), bidx + 3); p++; }
        }
    }
    __syncthreads();

    const int n = shN;
    const bool fast = (f0 <= 0.0f) && (n <= CAP);   // block-uniform
    int numTrain = 0;
    bool done = false;
    unsigned T = 0u; int nEq = 0;

    if (fast) {
        // ---- pass 0 over candidates: in-place fkey conversion + aggregated hist
        {
            int iters = (n + TPB - 1) / TPB;
            for (int it = 0; it < iters; it++) {
                int i = tid + it * TPB;
                bool act = i < n;
                unsigned am = __ballot_sync(0xffffffffu, act);
                if (act) {
                    unsigned k = fkey_raw(cand[i].x);
                    cand[i].x = k;
                    int b = (int)(k >> 24);
                    unsigned m = __match_any_sync(am, b);
                    if ((__ffs(m) - 1) == lane) atomicAdd(&h6[2][b], __popc(m));
                }
            }
        }
        __syncthreads();
        if (warp == 0) scan_count_cross(h6[2], &shPrefix, &shKK, &shNum);
        __syncthreads();
        numTrain = shNum;

        if (n >= numTrain) {        // block-uniform
            #pragma unroll 1
            for (int pp = 1; pp < 4; pp++) {
                const int shift = 24 - 8 * pp;
                const unsigned pref = shPrefix;
                const int kk = shKK;
                const unsigned prefHi = pref >> (shift + 8);
                for (int i = tid; i < n; i += TPB) {
                    unsigned k = cand[i].x;
                    if ((k >> (shift + 8)) == prefHi)
                        atomicAdd(&h6[2 + pp][(k >> shift) & 255u], 1);
                }
                __syncthreads();
                if (warp == 0) scan_crossing(h6[2 + pp], kk, pref, shift, &shPrefix, &shKK);
                __syncthreads();
            }
            T = shPrefix; nEq = shKK;

            // gather: >T into selA; ==T into eqA (index tie-break below)
            for (int i = tid; i < n; i += TPB) {
                uint2 c = cand[i];
                if (c.x > T)       { int p = atomicAdd(&shSel, 1); selA[p] = (int)c.y; }
                else if (c.x == T) { int p = atomicAdd(&shEq, 1); if (p < EQCAP) eqA[p] = (int)c.y; }
            }
            __syncthreads();
            int m = shEq;
            if (m <= EQCAP) {       // block-uniform
                for (int i = tid; i < m; i += TPB) {
                    int my = eqA[i], r = 0;
                    for (int j2 = 0; j2 < m; j2++) r += (eqA[j2] < my);
                    if (r < nEq) { int p = atomicAdd(&shSel, 1); selA[p] = my; }
                }
                __syncthreads();
                // rank the numTrain selected indices and write ascending, directly
                for (int i = tid; i < numTrain; i += TPB) {
                    int my = selA[i], r = 0;
                    for (int j2 = 0; j2 < numTrain; j2++) r += (selA[j2] < my);
                    cls_out[obase + r] = (float)my;
                }
                done = true;
            }
        }
    }

    if (!done) {
        // ---- Exact fallback: full 4-pass radix over gmem + ordered direct emission
        h6[0][tid] = 0;
        __syncthreads();
        for (int i = tid; i < KDIM; i += TPB)
            atomicAdd(&h6[0][fkey(rowp[i]) >> 24], 1);
        __syncthreads();
        if (warp == 0) scan_count_cross(h6[0], &shPrefix, &shKK, &shNum);
        __syncthreads();
        numTrain = shNum;

        #pragma unroll 1
        for (int pp = 1; pp < 4; pp++) {
            h6[0][tid] = 0;
            __syncthreads();
            const int shift = 24 - 8 * pp;
            const unsigned pref = shPrefix;
            const int kk = shKK;
            const unsigned prefHi = pref >> (shift + 8);
            for (int i = tid; i < KDIM; i += TPB) {
                unsigned k = fkey(rowp[i]);
                if ((k >> (shift + 8)) == prefHi)
                    atomicAdd(&h6[0][(k >> shift) & 255u], 1);
            }
            __syncthreads();
            if (warp == 0) scan_crossing(h6[0], kk, pref, shift, &shPrefix, &shKK);
            __syncthreads();
        }
        T = shPrefix; nEq = shKK;

        // ordered compaction: thread t owns elements [t*32, t*32+32)
        const float4* my4 = src4 + tid * 8;
        int cg = 0, ce = 0;
        #pragma unroll
        for (int j = 0; j < 8; j++) {
            float4 v = my4[j];
            unsigned k0 = fkey(v.x), k1 = fkey(v.y), k2 = fkey(v.z), k3 = fkey(v.w);
            cg += (k0 > T) + (k1 > T) + (k2 > T) + (k3 > T);
            ce += (k0 == T) + (k1 == T) + (k2 == T) + (k3 == T);
        }
        int pack = (cg << 16) | ce;
        int inc2 = pack;
        #pragma unroll
        for (int o = 1; o < 32; o <<= 1) {
            int t = __shfl_up_sync(0xffffffffu, inc2, o);
            if (lane >= o) inc2 += t;
        }
        if (lane == 31) warpTot[warp] = inc2;
        __syncthreads();
        int wOff = 0;
        #pragma unroll
        for (int w = 0; w < 8; w++) if (w < warp) wOff += warpTot[w];
        int exc = wOff + inc2 - pack;
        int g = exc >> 16;
        int e = exc & 0xFFFF;
        #pragma unroll
        for (int j = 0; j < 8; j++) {
            float4 v = my4[j];
            #pragma unroll
            for (int c = 0; c < 4; c++) {
                float f = (c == 0) ? v.x : (c == 1) ? v.y : (c == 2) ? v.z : v.w;
                unsigned k = fkey(f);
                int idx = tid * 32 + j * 4 + c;
                if (k > T)       { cls_out[obase + g + min(e, nEq)] = (float)idx; g++; }
                else if (k == T) { if (e < nEq) cls_out[obase + g + e] = (float)idx; e++; }
            }
        }
    }

    // ---- Emit bs/mask + cls padding (numTrain valid from shNum via barriers above)
    if (tid < MAXC) {
        bool valid = tid < numTrain;
        size_t o = obase + tid;
        bs_out[o]   = valid ? (float)row : -1.0f;
        mask_out[o] = valid ? 1.0f : 0.0f;
        if (!valid) cls_out[o] = -1.0f;
    }
}

extern "C" void kernel_launch(void* const* d_in, const int* in_sizes, int n_in,
                              void* d_out, int out_size) {
    const float* logits = (const float*)d_in[0];
    const int total = in_sizes[0];
    const int bs = total / KDIM;
    const size_t per = (size_t)bs * MAXC;

    float* out = (float*)d_out;
    float* bs_out   = out;
    float* cls_out  = out + per;
    float* mask_out = out + 2 * per;

    retention_kernel<<<bs, TPB>>>(logits, bs_out, cls_out, mask_out);
}